// round 1
// baseline (speedup 1.0000x reference)
#include <cuda_runtime.h>
#include <cuda_bf16.h>

#define H 128
#define HV4 32           // H / 4
#define NMAX 100000
#define TILE_ROWS 64
#define MLP_THREADS 256
#define MLP_SMEM (196608)  // W1s 64KB + W2s 64KB + Hs 32KB + Ts 32KB

// Scratch (device globals: no allocation allowed)
__device__ __align__(16) float g_x[(size_t)NMAX * H];
__device__ __align__(16) float g_h[(size_t)NMAX * H];

// ---------------------------------------------------------------------------
// Embedding gather: x[i] = emb[z[i]], h[i] = x[i]  (h pre-initialized so the
// edge kernel's atomic accumulation directly produces h = x + agg)
// ---------------------------------------------------------------------------
__global__ void embed_kernel(const float* __restrict__ emb,
                             const int* __restrict__ z,
                             float* __restrict__ x, float* __restrict__ h,
                             int n) {
    int i = blockIdx.x * blockDim.x + threadIdx.x;
    if (i >= n * HV4) return;
    int node = i >> 5;
    int c = i & 31;
    float4 v = ((const float4*)emb)[(size_t)z[node] * HV4 + c];
    ((float4*)x)[i] = v;
    ((float4*)h)[i] = v;
}

// ---------------------------------------------------------------------------
// Edge/message kernel (one warp per edge, lane handles 4 channels):
//   e    = edge_attr[e] @ We + be        (4 FMAs per channel, We in smem)
//   m    = relu(x[src] + e)
//   h[dst] += m  via red.global.add.v4.f32
// ---------------------------------------------------------------------------
__global__ void edge_kernel(const float* __restrict__ x,
                            float* __restrict__ h,
                            const float* __restrict__ edge_attr,
                            const int* __restrict__ ei,   // [2, E]
                            const float* __restrict__ We, // [4, 128]
                            const float* __restrict__ be, // [128]
                            int E) {
    __shared__ float Wes[4 * H];
    __shared__ float bes[H];
    int tid = threadIdx.x;
    for (int i = tid; i < 4 * H; i += blockDim.x) Wes[i] = We[i];
    for (int i = tid; i < H; i += blockDim.x) bes[i] = be[i];
    __syncthreads();

    int lane = tid & 31;
    int warp = blockIdx.x * (blockDim.x >> 5) + (tid >> 5);
    int nwarps = gridDim.x * (blockDim.x >> 5);

    float4 w0 = ((const float4*)Wes)[0 * HV4 + lane];
    float4 w1 = ((const float4*)Wes)[1 * HV4 + lane];
    float4 w2 = ((const float4*)Wes)[2 * HV4 + lane];
    float4 w3 = ((const float4*)Wes)[3 * HV4 + lane];
    float4 bb = ((const float4*)bes)[lane];

    for (int e = warp; e < E; e += nwarps) {
        int src = ei[e];
        int dst = ei[E + e];
        float4 ea = ((const float4*)edge_attr)[e];
        float4 xv = ((const float4*)x)[(size_t)src * HV4 + lane];

        float m0 = xv.x + bb.x + ea.x * w0.x + ea.y * w1.x + ea.z * w2.x + ea.w * w3.x;
        float m1 = xv.y + bb.y + ea.x * w0.y + ea.y * w1.y + ea.z * w2.y + ea.w * w3.y;
        float m2 = xv.z + bb.z + ea.x * w0.z + ea.y * w1.z + ea.z * w2.z + ea.w * w3.z;
        float m3 = xv.w + bb.w + ea.x * w0.w + ea.y * w1.w + ea.z * w2.w + ea.w * w3.w;
        m0 = fmaxf(m0, 0.f); m1 = fmaxf(m1, 0.f);
        m2 = fmaxf(m2, 0.f); m3 = fmaxf(m3, 0.f);

        float* dptr = h + (size_t)dst * H + lane * 4;
        asm volatile("red.global.add.v4.f32 [%0], {%1,%2,%3,%4};"
                     :: "l"(dptr), "f"(m0), "f"(m1), "f"(m2), "f"(m3)
                     : "memory");
    }
}

// ---------------------------------------------------------------------------
// Fused 2-layer MLP: x_out = silu(h @ W1 + b1) @ W2 + b2
// Persistent blocks, both weight matrices resident in smem (128KB),
// 64-row tiles, 8x4 register tile per thread (256 threads).
// Thread map: cg = tid&31 -> cols cg*4..cg*4+3 ; rg = tid>>5 -> rows rg*8..rg*8+7
// ---------------------------------------------------------------------------
__global__ void __launch_bounds__(MLP_THREADS, 1)
mlp_kernel(const float* __restrict__ h_in,
           const float* __restrict__ W1, const float* __restrict__ b1,
           const float* __restrict__ W2, const float* __restrict__ b2,
           float* __restrict__ x_out, float* __restrict__ h_out,
           int n) {
    extern __shared__ float sm[];
    float* W1s = sm;                 // 16384 floats
    float* W2s = sm + 16384;         // 16384 floats
    float* Hs  = sm + 32768;         // 64*128 floats
    float* Ts  = sm + 32768 + 8192;  // 64*128 floats

    int tid = threadIdx.x;
    for (int i = tid; i < 16384 / 4; i += MLP_THREADS) {
        ((float4*)W1s)[i] = ((const float4*)W1)[i];
        ((float4*)W2s)[i] = ((const float4*)W2)[i];
    }
    int cg = tid & 31;
    int rg = tid >> 5;
    float4 bb1 = ((const float4*)b1)[cg];
    float4 bb2 = ((const float4*)b2)[cg];
    __syncthreads();

    int ntiles = (n + TILE_ROWS - 1) / TILE_ROWS;
    for (int t = blockIdx.x; t < ntiles; t += gridDim.x) {
        int row0 = t * TILE_ROWS;

        // load H tile (zero-pad out-of-range rows)
        for (int i = tid; i < TILE_ROWS * HV4; i += MLP_THREADS) {
            int r = i >> 5;
            int c = i & 31;
            int row = row0 + r;
            float4 v = make_float4(0.f, 0.f, 0.f, 0.f);
            if (row < n) v = ((const float4*)h_in)[(size_t)row * HV4 + c];
            ((float4*)Hs)[i] = v;
        }
        __syncthreads();

        // ---- stage A: T = silu(H @ W1 + b1) ----
        float acc[8][4];
        #pragma unroll
        for (int r = 0; r < 8; r++) {
            acc[r][0] = bb1.x; acc[r][1] = bb1.y;
            acc[r][2] = bb1.z; acc[r][3] = bb1.w;
        }
        #pragma unroll 4
        for (int k = 0; k < H; k++) {
            float4 b4 = ((const float4*)W1s)[k * HV4 + cg];
            #pragma unroll
            for (int r = 0; r < 8; r++) {
                float a = Hs[(rg * 8 + r) * H + k];
                acc[r][0] += a * b4.x; acc[r][1] += a * b4.y;
                acc[r][2] += a * b4.z; acc[r][3] += a * b4.w;
            }
        }
        #pragma unroll
        for (int r = 0; r < 8; r++) {
            float4 v;
            v.x = acc[r][0] / (1.f + __expf(-acc[r][0]));
            v.y = acc[r][1] / (1.f + __expf(-acc[r][1]));
            v.z = acc[r][2] / (1.f + __expf(-acc[r][2]));
            v.w = acc[r][3] / (1.f + __expf(-acc[r][3]));
            ((float4*)Ts)[(rg * 8 + r) * HV4 + cg] = v;
        }
        __syncthreads();

        // ---- stage B: out = T @ W2 + b2 ----
        #pragma unroll
        for (int r = 0; r < 8; r++) {
            acc[r][0] = bb2.x; acc[r][1] = bb2.y;
            acc[r][2] = bb2.z; acc[r][3] = bb2.w;
        }
        #pragma unroll 4
        for (int k = 0; k < H; k++) {
            float4 b4 = ((const float4*)W2s)[k * HV4 + cg];
            #pragma unroll
            for (int r = 0; r < 8; r++) {
                float a = Ts[(rg * 8 + r) * H + k];
                acc[r][0] += a * b4.x; acc[r][1] += a * b4.y;
                acc[r][2] += a * b4.z; acc[r][3] += a * b4.w;
            }
        }
        #pragma unroll
        for (int r = 0; r < 8; r++) {
            int row = row0 + rg * 8 + r;
            if (row < n) {
                float4 v = make_float4(acc[r][0], acc[r][1], acc[r][2], acc[r][3]);
                ((float4*)x_out)[(size_t)row * HV4 + cg] = v;
                if (h_out) ((float4*)h_out)[(size_t)row * HV4 + cg] = v;
            }
        }
        // next-iteration barriers (Hs-load sync + A->B sync) make further
        // synchronization here unnecessary
    }
}

// batch_vec -> float tail of the output
__global__ void batch_kernel(const int* __restrict__ bv, float* __restrict__ out, int n) {
    int i = blockIdx.x * blockDim.x + threadIdx.x;
    if (i < n) out[i] = (float)bv[i];
}

extern "C" void kernel_launch(void* const* d_in, const int* in_sizes, int n_in,
                              void* d_out, int out_size) {
    const float* emb       = (const float*)d_in[0];   // [100,128]
    const float* We        = (const float*)d_in[1];   // [3,4,128]
    const float* be        = (const float*)d_in[2];   // [3,128]
    const float* W1        = (const float*)d_in[3];   // [3,128,128]
    const float* b1        = (const float*)d_in[4];   // [3,128]
    const float* W2        = (const float*)d_in[5];   // [3,128,128]
    const float* b2        = (const float*)d_in[6];   // [3,128]
    const float* edge_attr = (const float*)d_in[7];   // [E,4]
    const int*   z         = (const int*)d_in[8];     // [N]
    const int*   ei        = (const int*)d_in[9];     // [2,E]
    const int*   bv        = (const int*)d_in[10];    // [N]

    int n = in_sizes[8];
    int E = in_sizes[9] / 2;
    float* out = (float*)d_out;

    float *gx, *gh;
    cudaGetSymbolAddress((void**)&gx, g_x);
    cudaGetSymbolAddress((void**)&gh, g_h);

    cudaFuncSetAttribute(mlp_kernel, cudaFuncAttributeMaxDynamicSharedMemorySize,
                         MLP_SMEM);

    embed_kernel<<<(n * HV4 + 255) / 256, 256>>>(emb, z, gx, gh, n);

    for (int l = 0; l < 3; l++) {
        edge_kernel<<<4096, 256>>>(gx, gh, edge_attr, ei,
                                   We + (size_t)l * 4 * H, be + (size_t)l * H, E);
        bool last = (l == 2);
        mlp_kernel<<<148, MLP_THREADS, MLP_SMEM>>>(
            gh,
            W1 + (size_t)l * H * H, b1 + (size_t)l * H,
            W2 + (size_t)l * H * H, b2 + (size_t)l * H,
            last ? out : gx,
            last ? nullptr : gh,
            n);
    }

    if (out_size >= n * H + n) {
        batch_kernel<<<(n + 255) / 256, 256>>>(bv, out + (size_t)n * H, n);
    }
}

// round 3
// speedup vs baseline: 1.3882x; 1.3882x over previous
#include <cuda_runtime.h>
#include <cuda_bf16.h>
#include <cstdint>

#define H 128
#define NMAX 100000
#define TM 128
#define MLP_THREADS 256
#define ROWSTRIDE 68                       // u32 per row (conflict padding)
#define MLP_SMEM (4 * 128 * ROWSTRIDE * 4) // Hs_hi, Hs_lo, Ts_hi, Ts_lo

// Scratch (device globals: no allocation allowed)
__device__ __align__(16) float g_x[(size_t)NMAX * H];
__device__ __align__(16) float g_h[(size_t)NMAX * H];
// weight fragments: [layer][warp 8][img 4][nb 2][ks 8][lane 32][2] u32
__device__ __align__(16) uint32_t g_wfrag[3 * 8 * 4 * 2 * 8 * 32 * 2];

__device__ __forceinline__ uint32_t pack_bf16(float x, float y) {
    __nv_bfloat162 t = __floats2bfloat162_rn(x, y);
    return *(uint32_t*)&t;
}
// permuted pair index: pair j (cols 2j,2j+1) -> slot so that a0/a2 are adjacent
__device__ __forceinline__ int pidx(int j) {
    return ((j >> 3) << 3) + ((j & 3) << 1) + ((j >> 2) & 1);
}

#define MMA_BF16(c, A0, A1, A2, A3, B0, B1)                                   \
    asm volatile("mma.sync.aligned.m16n8k16.row.col.f32.bf16.bf16.f32 "       \
                 "{%0,%1,%2,%3}, {%4,%5,%6,%7}, {%8,%9}, {%0,%1,%2,%3};"      \
                 : "+f"(c[0]), "+f"(c[1]), "+f"(c[2]), "+f"(c[3])             \
                 : "r"(A0), "r"(A1), "r"(A2), "r"(A3), "r"(B0), "r"(B1));

// ---------------------------------------------------------------------------
// Weight prep: split W1/W2 (f32 [k][n]) into bf16 hi/lo mma B-fragments,
// laid out exactly in the per-warp register-load order.
// ---------------------------------------------------------------------------
__global__ void wprep_kernel(const float* __restrict__ W1,
                             const float* __restrict__ W2) {
    int idx = blockIdx.x * blockDim.x + threadIdx.x;
    if (idx >= 3 * 8 * 4 * 2 * 8 * 32 * 2) return;
    int r    = idx & 1;
    int lane = (idx >> 1) & 31;
    int ks   = (idx >> 6) & 7;
    int nb   = (idx >> 9) & 1;
    int img  = (idx >> 10) & 3;
    int w    = (idx >> 12) & 7;
    int l    = idx >> 15;
    int gid = lane >> 2, tg = lane & 3;
    int mat = img >> 1, hl = img & 1;
    int n  = w * 16 + nb * 8 + gid;
    int k0 = ks * 16 + tg * 2 + r * 8;
    const float* W = (mat ? W2 : W1) + (size_t)l * H * H;
    float v0 = W[k0 * H + n];
    float v1 = W[(k0 + 1) * H + n];
    __nv_bfloat16 h0 = __float2bfloat16(v0);
    __nv_bfloat16 h1 = __float2bfloat16(v1);
    float o0 = hl ? (v0 - __bfloat162float(h0)) : __bfloat162float(h0);
    float o1 = hl ? (v1 - __bfloat162float(h1)) : __bfloat162float(h1);
    g_wfrag[idx] = pack_bf16(o0, o1);
}

// ---------------------------------------------------------------------------
// Embedding gather
// ---------------------------------------------------------------------------
__global__ void embed_kernel(const float* __restrict__ emb,
                             const int* __restrict__ z,
                             float* __restrict__ x, float* __restrict__ h,
                             int n) {
    int i = blockIdx.x * blockDim.x + threadIdx.x;
    if (i >= n * 32) return;
    int node = i >> 5;
    int c = i & 31;
    float4 v = ((const float4*)emb)[(size_t)z[node] * 32 + c];
    ((float4*)x)[i] = v;
    ((float4*)h)[i] = v;
}

// ---------------------------------------------------------------------------
// Edge/message kernel (one warp per edge, lane handles 4 channels)
// ---------------------------------------------------------------------------
__global__ void edge_kernel(const float* __restrict__ x,
                            float* __restrict__ h,
                            const float* __restrict__ edge_attr,
                            const int* __restrict__ ei,
                            const float* __restrict__ We,
                            const float* __restrict__ be,
                            int E) {
    __shared__ float Wes[4 * H];
    __shared__ float bes[H];
    int tid = threadIdx.x;
    for (int i = tid; i < 4 * H; i += blockDim.x) Wes[i] = We[i];
    for (int i = tid; i < H; i += blockDim.x) bes[i] = be[i];
    __syncthreads();

    int lane = tid & 31;
    int warp = blockIdx.x * (blockDim.x >> 5) + (tid >> 5);
    int nwarps = gridDim.x * (blockDim.x >> 5);

    float4 w0 = ((const float4*)Wes)[0 * 32 + lane];
    float4 w1 = ((const float4*)Wes)[1 * 32 + lane];
    float4 w2 = ((const float4*)Wes)[2 * 32 + lane];
    float4 w3 = ((const float4*)Wes)[3 * 32 + lane];
    float4 bb = ((const float4*)bes)[lane];

    for (int e = warp; e < E; e += nwarps) {
        int src = ei[e];
        int dst = ei[E + e];
        float4 ea = ((const float4*)edge_attr)[e];
        float4 xv = ((const float4*)x)[(size_t)src * 32 + lane];

        float m0 = xv.x + bb.x + ea.x * w0.x + ea.y * w1.x + ea.z * w2.x + ea.w * w3.x;
        float m1 = xv.y + bb.y + ea.x * w0.y + ea.y * w1.y + ea.z * w2.y + ea.w * w3.y;
        float m2 = xv.z + bb.z + ea.x * w0.z + ea.y * w1.z + ea.z * w2.z + ea.w * w3.z;
        float m3 = xv.w + bb.w + ea.x * w0.w + ea.y * w1.w + ea.z * w2.w + ea.w * w3.w;
        m0 = fmaxf(m0, 0.f); m1 = fmaxf(m1, 0.f);
        m2 = fmaxf(m2, 0.f); m3 = fmaxf(m3, 0.f);

        float* dptr = h + (size_t)dst * H + lane * 4;
        asm volatile("red.global.add.v4.f32 [%0], {%1,%2,%3,%4};"
                     :: "l"(dptr), "f"(m0), "f"(m1), "f"(m2), "f"(m3)
                     : "memory");
    }
}

// ---------------------------------------------------------------------------
// Fused 2-layer MLP via mma.sync bf16x3 (fp32-accurate split):
//   D = Ah*Bh + Al*Bh + Ah*Bl
// Persistent CTAs, 128-row tiles. Each of 8 warps owns a 16-col slice and
// keeps all four weight images (W1h/W1l/W2h/W2l) for its slice in registers.
// ---------------------------------------------------------------------------
__global__ void __launch_bounds__(MLP_THREADS, 1)
mlp_kernel(const float* __restrict__ h_in,
           const uint32_t* __restrict__ wfrag,  // this layer's fragments
           const float* __restrict__ b1, const float* __restrict__ b2,
           float* __restrict__ x_out, float* __restrict__ h_out, int n) {
    extern __shared__ __align__(16) uint32_t sm[];
    uint32_t* Hs_hi = sm;
    uint32_t* Hs_lo = sm + 128 * ROWSTRIDE;
    uint32_t* Ts_hi = sm + 2 * 128 * ROWSTRIDE;
    uint32_t* Ts_lo = sm + 3 * 128 * ROWSTRIDE;

    int tid = threadIdx.x, w = tid >> 5, lane = tid & 31;
    int gid = lane >> 2, tg = lane & 3;

    // load this warp's weight fragments into registers (128 u32)
    uint2 wB[4][2][8];
    {
        const uint2* wp = (const uint2*)wfrag + (size_t)w * 4 * 2 * 8 * 32;
        #pragma unroll
        for (int img = 0; img < 4; img++)
            #pragma unroll
            for (int nb = 0; nb < 2; nb++)
                #pragma unroll
                for (int ks = 0; ks < 8; ks++)
                    wB[img][nb][ks] = wp[(((img * 2) + nb) * 8 + ks) * 32 + lane];
    }
    float2 b1v[2], b2v[2];
    #pragma unroll
    for (int nb = 0; nb < 2; nb++) {
        b1v[nb] = *(const float2*)(b1 + 16 * w + 8 * nb + 2 * tg);
        b2v[nb] = *(const float2*)(b2 + 16 * w + 8 * nb + 2 * tg);
    }

    int ntiles = (n + TM - 1) / TM;
    for (int t = blockIdx.x; t < ntiles; t += gridDim.x) {
        int row0 = t * TM;

        // ---- stage H tile into smem as bf16 hi/lo packed pairs ----
        #pragma unroll 4
        for (int it = 0; it < 16; it++) {
            int i = tid + it * MLP_THREADS;   // 4096 float4 total
            int row = i >> 5;
            int c4 = i & 31;
            int grow = row0 + row;
            float4 v = make_float4(0.f, 0.f, 0.f, 0.f);
            if (grow < n) v = ((const float4*)h_in)[(size_t)grow * 32 + c4];
            __nv_bfloat16 hx = __float2bfloat16(v.x), hy = __float2bfloat16(v.y);
            __nv_bfloat16 hz = __float2bfloat16(v.z), hw = __float2bfloat16(v.w);
            int base = row * ROWSTRIDE;
            int p0 = pidx(2 * c4), p1 = pidx(2 * c4 + 1);
            Hs_hi[base + p0] = pack_bf16(__bfloat162float(hx), __bfloat162float(hy));
            Hs_hi[base + p1] = pack_bf16(__bfloat162float(hz), __bfloat162float(hw));
            Hs_lo[base + p0] = pack_bf16(v.x - __bfloat162float(hx), v.y - __bfloat162float(hy));
            Hs_lo[base + p1] = pack_bf16(v.z - __bfloat162float(hz), v.w - __bfloat162float(hw));
        }
        __syncthreads();

        // ---- GEMM1: T = silu(H @ W1 + b1) -> Ts (bf16 hi/lo) ----
        #pragma unroll 1
        for (int mb = 0; mb < 8; mb++) {
            float acc[2][4] = {{0.f, 0.f, 0.f, 0.f}, {0.f, 0.f, 0.f, 0.f}};
            int ra = (mb * 16 + gid) * ROWSTRIDE;
            int rb = ra + 8 * ROWSTRIDE;
            #pragma unroll
            for (int ks = 0; ks < 8; ks++) {
                uint2 ah = *(const uint2*)(Hs_hi + ra + ks * 8 + tg * 2);
                uint2 ahb = *(const uint2*)(Hs_hi + rb + ks * 8 + tg * 2);
                uint2 al = *(const uint2*)(Hs_lo + ra + ks * 8 + tg * 2);
                uint2 alb = *(const uint2*)(Hs_lo + rb + ks * 8 + tg * 2);
                #pragma unroll
                for (int nb = 0; nb < 2; nb++) {
                    uint2 bh = wB[0][nb][ks];
                    uint2 bl = wB[1][nb][ks];
                    MMA_BF16(acc[nb], ah.x, ahb.x, ah.y, ahb.y, bh.x, bh.y);
                    MMA_BF16(acc[nb], al.x, alb.x, al.y, alb.y, bh.x, bh.y);
                    MMA_BF16(acc[nb], ah.x, ahb.x, ah.y, ahb.y, bl.x, bl.y);
                }
            }
            int sa = (mb * 16 + gid) * ROWSTRIDE + 8 * w + 2 * tg;
            int sb = sa + 8 * ROWSTRIDE;
            #pragma unroll
            for (int nb = 0; nb < 2; nb++) {
                float f0 = acc[nb][0] + b1v[nb].x;
                float f1 = acc[nb][1] + b1v[nb].y;
                float f2 = acc[nb][2] + b1v[nb].x;
                float f3 = acc[nb][3] + b1v[nb].y;
                f0 = f0 / (1.f + __expf(-f0));
                f1 = f1 / (1.f + __expf(-f1));
                f2 = f2 / (1.f + __expf(-f2));
                f3 = f3 / (1.f + __expf(-f3));
                __nv_bfloat16 h0 = __float2bfloat16(f0), h1 = __float2bfloat16(f1);
                __nv_bfloat16 h2 = __float2bfloat16(f2), h3 = __float2bfloat16(f3);
                Ts_hi[sa + nb] = pack_bf16(__bfloat162float(h0), __bfloat162float(h1));
                Ts_hi[sb + nb] = pack_bf16(__bfloat162float(h2), __bfloat162float(h3));
                Ts_lo[sa + nb] = pack_bf16(f0 - __bfloat162float(h0), f1 - __bfloat162float(h1));
                Ts_lo[sb + nb] = pack_bf16(f2 - __bfloat162float(h2), f3 - __bfloat162float(h3));
            }
        }
        __syncthreads();

        // ---- GEMM2: out = T @ W2 + b2 -> gmem ----
        #pragma unroll 1
        for (int mb = 0; mb < 8; mb++) {
            float acc[2][4] = {{0.f, 0.f, 0.f, 0.f}, {0.f, 0.f, 0.f, 0.f}};
            int ra = (mb * 16 + gid) * ROWSTRIDE;
            int rb = ra + 8 * ROWSTRIDE;
            #pragma unroll
            for (int ks = 0; ks < 8; ks++) {
                uint2 ah = *(const uint2*)(Ts_hi + ra + ks * 8 + tg * 2);
                uint2 ahb = *(const uint2*)(Ts_hi + rb + ks * 8 + tg * 2);
                uint2 al = *(const uint2*)(Ts_lo + ra + ks * 8 + tg * 2);
                uint2 alb = *(const uint2*)(Ts_lo + rb + ks * 8 + tg * 2);
                #pragma unroll
                for (int nb = 0; nb < 2; nb++) {
                    uint2 bh = wB[2][nb][ks];
                    uint2 bl = wB[3][nb][ks];
                    MMA_BF16(acc[nb], ah.x, ahb.x, ah.y, ahb.y, bh.x, bh.y);
                    MMA_BF16(acc[nb], al.x, alb.x, al.y, alb.y, bh.x, bh.y);
                    MMA_BF16(acc[nb], ah.x, ahb.x, ah.y, ahb.y, bl.x, bl.y);
                }
            }
            int r0 = row0 + mb * 16 + gid;
            int r1 = r0 + 8;
            #pragma unroll
            for (int nb = 0; nb < 2; nb++) {
                int col = 16 * w + 8 * nb + 2 * tg;
                if (r0 < n) {
                    float2 o0 = make_float2(acc[nb][0] + b2v[nb].x,
                                            acc[nb][1] + b2v[nb].y);
                    *(float2*)(x_out + (size_t)r0 * H + col) = o0;
                    if (h_out) *(float2*)(h_out + (size_t)r0 * H + col) = o0;
                }
                if (r1 < n) {
                    float2 o1 = make_float2(acc[nb][2] + b2v[nb].x,
                                            acc[nb][3] + b2v[nb].y);
                    *(float2*)(x_out + (size_t)r1 * H + col) = o1;
                    if (h_out) *(float2*)(h_out + (size_t)r1 * H + col) = o1;
                }
            }
        }
        __syncthreads();
    }
}

// batch_vec -> float tail of the output
__global__ void batch_kernel(const int* __restrict__ bv, float* __restrict__ out, int n) {
    int i = blockIdx.x * blockDim.x + threadIdx.x;
    if (i < n) out[i] = (float)bv[i];
}

extern "C" void kernel_launch(void* const* d_in, const int* in_sizes, int n_in,
                              void* d_out, int out_size) {
    const float* emb       = (const float*)d_in[0];
    const float* We        = (const float*)d_in[1];
    const float* be        = (const float*)d_in[2];
    const float* W1        = (const float*)d_in[3];
    const float* b1        = (const float*)d_in[4];
    const float* W2        = (const float*)d_in[5];
    const float* b2        = (const float*)d_in[6];
    const float* edge_attr = (const float*)d_in[7];
    const int*   z         = (const int*)d_in[8];
    const int*   ei        = (const int*)d_in[9];
    const int*   bv        = (const int*)d_in[10];

    int n = in_sizes[8];
    int E = in_sizes[9] / 2;
    float* out = (float*)d_out;

    float *gx, *gh;
    uint32_t* gwf;
    cudaGetSymbolAddress((void**)&gx, g_x);
    cudaGetSymbolAddress((void**)&gh, g_h);
    cudaGetSymbolAddress((void**)&gwf, g_wfrag);

    cudaFuncSetAttribute(mlp_kernel, cudaFuncAttributeMaxDynamicSharedMemorySize,
                         MLP_SMEM);

    wprep_kernel<<<(3 * 8 * 4 * 2 * 8 * 32 * 2 + 255) / 256, 256>>>(W1, W2);
    embed_kernel<<<(n * 32 + 255) / 256, 256>>>(emb, z, gx, gh, n);

    for (int l = 0; l < 3; l++) {
        edge_kernel<<<4096, 256>>>(gx, gh, edge_attr, ei,
                                   We + (size_t)l * 4 * H, be + (size_t)l * H, E);
        bool last = (l == 2);
        mlp_kernel<<<148, MLP_THREADS, MLP_SMEM>>>(
            gh,
            gwf + (size_t)l * 8 * 4 * 2 * 8 * 32 * 2,
            b1 + (size_t)l * H, b2 + (size_t)l * H,
            last ? out : gx,
            last ? nullptr : gh,
            n);
    }

    if (out_size >= n * H + n) {
        batch_kernel<<<(n + 255) / 256, 256>>>(bv, out + (size_t)n * H, n);
    }
}

// round 4
// speedup vs baseline: 1.7650x; 1.2714x over previous
#include <cuda_runtime.h>
#include <cuda_bf16.h>
#include <cstdint>

#define H 128
#define NMAX 100000
#define TM 128
#define MLP_THREADS 256
#define ROWSTRIDE 68                        // u32 per row (conflict padding)
#define STAGE_OFF (4 * 128 * ROWSTRIDE)     // u32 offset of f32 stage buffer
#define MLP_SMEM (STAGE_OFF * 4 + 128 * 128 * 4)  // 139264 + 65536 = 204800 B

// Scratch (device globals: no allocation allowed)
__device__ __align__(16) float g_x[(size_t)NMAX * H];
__device__ __align__(16) float g_h[(size_t)NMAX * H];
// weight fragments: [layer][warp 8][img 4][nb 2][ks 8][lane 32][2] u32
__device__ __align__(16) uint32_t g_wfrag[3 * 8 * 4 * 2 * 8 * 32 * 2];

__device__ __forceinline__ uint32_t pack_bf16(float x, float y) {
    __nv_bfloat162 t = __floats2bfloat162_rn(x, y);
    return *(uint32_t*)&t;
}
// permuted pair index: pair j (cols 2j,2j+1) -> slot so that a0/a2 are adjacent
__device__ __forceinline__ int pidx(int j) {
    return ((j >> 3) << 3) + ((j & 3) << 1) + ((j >> 2) & 1);
}
__device__ __forceinline__ uint32_t smem_u32(const void* p) {
    uint32_t a;
    asm("{ .reg .u64 t; cvta.to.shared.u64 t, %1; cvt.u32.u64 %0, t; }" : "=r"(a) : "l"(p));
    return a;
}
__device__ __forceinline__ float silu_fast(float f) {
    float th;
    asm("tanh.approx.f32 %0, %1;" : "=f"(th) : "f"(0.5f * f));
    return f * fmaf(0.5f, th, 0.5f);
}

#define MMA_BF16(c, A0, A1, A2, A3, B0, B1)                                   \
    asm volatile("mma.sync.aligned.m16n8k16.row.col.f32.bf16.bf16.f32 "       \
                 "{%0,%1,%2,%3}, {%4,%5,%6,%7}, {%8,%9}, {%0,%1,%2,%3};"      \
                 : "+f"(c[0]), "+f"(c[1]), "+f"(c[2]), "+f"(c[3])             \
                 : "r"(A0), "r"(A1), "r"(A2), "r"(A3), "r"(B0), "r"(B1));

// ---------------------------------------------------------------------------
// Weight prep: split W1/W2 (f32 [k][n]) into bf16 hi/lo mma B-fragments,
// laid out exactly in the per-warp register-load order.
// ---------------------------------------------------------------------------
__global__ void wprep_kernel(const float* __restrict__ W1,
                             const float* __restrict__ W2) {
    int idx = blockIdx.x * blockDim.x + threadIdx.x;
    if (idx >= 3 * 8 * 4 * 2 * 8 * 32 * 2) return;
    int r    = idx & 1;
    int lane = (idx >> 1) & 31;
    int ks   = (idx >> 6) & 7;
    int nb   = (idx >> 9) & 1;
    int img  = (idx >> 10) & 3;
    int w    = (idx >> 12) & 7;
    int l    = idx >> 15;
    int gid = lane >> 2, tg = lane & 3;
    int mat = img >> 1, hl = img & 1;
    int n  = w * 16 + nb * 8 + gid;
    int k0 = ks * 16 + tg * 2 + r * 8;
    const float* W = (mat ? W2 : W1) + (size_t)l * H * H;
    float v0 = W[k0 * H + n];
    float v1 = W[(k0 + 1) * H + n];
    __nv_bfloat16 h0 = __float2bfloat16(v0);
    __nv_bfloat16 h1 = __float2bfloat16(v1);
    float o0 = hl ? (v0 - __bfloat162float(h0)) : __bfloat162float(h0);
    float o1 = hl ? (v1 - __bfloat162float(h1)) : __bfloat162float(h1);
    g_wfrag[idx] = pack_bf16(o0, o1);
}

// ---------------------------------------------------------------------------
// Embedding gather
// ---------------------------------------------------------------------------
__global__ void embed_kernel(const float* __restrict__ emb,
                             const int* __restrict__ z,
                             float* __restrict__ x, float* __restrict__ h,
                             int n) {
    int i = blockIdx.x * blockDim.x + threadIdx.x;
    if (i >= n * 32) return;
    int node = i >> 5;
    int c = i & 31;
    float4 v = ((const float4*)emb)[(size_t)z[node] * 32 + c];
    ((float4*)x)[i] = v;
    ((float4*)h)[i] = v;
}

// ---------------------------------------------------------------------------
// Edge/message kernel: one warp per 4 edges (pipelined), lane = 4 channels.
//   e = edge_attr @ We + be ; m = relu(x[src] + e) ; h[dst] += m (red.v4)
// ---------------------------------------------------------------------------
__global__ void edge_kernel(const float* __restrict__ x,
                            float* __restrict__ h,
                            const float* __restrict__ edge_attr,
                            const int* __restrict__ ei,
                            const float* __restrict__ We,
                            const float* __restrict__ be,
                            int E) {
    __shared__ float Wes[4 * H];
    __shared__ float bes[H];
    int tid = threadIdx.x;
    for (int i = tid; i < 4 * H; i += blockDim.x) Wes[i] = We[i];
    for (int i = tid; i < H; i += blockDim.x) bes[i] = be[i];
    __syncthreads();

    int lane = tid & 31;
    int warp = blockIdx.x * (blockDim.x >> 5) + (tid >> 5);
    int nwarps = gridDim.x * (blockDim.x >> 5);

    float4 w0 = ((const float4*)Wes)[0 * 32 + lane];
    float4 w1 = ((const float4*)Wes)[1 * 32 + lane];
    float4 w2 = ((const float4*)Wes)[2 * 32 + lane];
    float4 w3 = ((const float4*)Wes)[3 * 32 + lane];
    float4 bb = ((const float4*)bes)[lane];

    int stride = nwarps * 4;
    #pragma unroll 1
    for (int e0 = warp * 4; e0 < E; e0 += stride) {
        int ne = E - e0; if (ne > 4) ne = 4;
        int s[4], d[4];
        float4 ea[4], xv[4];
        #pragma unroll
        for (int j = 0; j < 4; j++)
            if (j < ne) { s[j] = ei[e0 + j]; d[j] = ei[E + e0 + j]; }
        #pragma unroll
        for (int j = 0; j < 4; j++)
            if (j < ne) ea[j] = ((const float4*)edge_attr)[e0 + j];
        #pragma unroll
        for (int j = 0; j < 4; j++)
            if (j < ne) xv[j] = ((const float4*)x)[(size_t)s[j] * 32 + lane];
        #pragma unroll
        for (int j = 0; j < 4; j++) {
            if (j >= ne) break;
            float m0 = xv[j].x + bb.x + ea[j].x * w0.x + ea[j].y * w1.x + ea[j].z * w2.x + ea[j].w * w3.x;
            float m1 = xv[j].y + bb.y + ea[j].x * w0.y + ea[j].y * w1.y + ea[j].z * w2.y + ea[j].w * w3.y;
            float m2 = xv[j].z + bb.z + ea[j].x * w0.z + ea[j].y * w1.z + ea[j].z * w2.z + ea[j].w * w3.z;
            float m3 = xv[j].w + bb.w + ea[j].x * w0.w + ea[j].y * w1.w + ea[j].z * w2.w + ea[j].w * w3.w;
            m0 = fmaxf(m0, 0.f); m1 = fmaxf(m1, 0.f);
            m2 = fmaxf(m2, 0.f); m3 = fmaxf(m3, 0.f);
            float* dptr = h + (size_t)d[j] * H + lane * 4;
            asm volatile("red.global.add.v4.f32 [%0], {%1,%2,%3,%4};"
                         :: "l"(dptr), "f"(m0), "f"(m1), "f"(m2), "f"(m3)
                         : "memory");
        }
    }
}

// ---------------------------------------------------------------------------
// Fused 2-layer MLP via mma.sync bf16x3: D = Ah*Bh + Al*Bh + Ah*Bl
// Persistent CTAs, 128-row tiles, cp.async-prefetched stage buffer,
// tanh-based silu (1 MUFU/value).
// ---------------------------------------------------------------------------
__global__ void __launch_bounds__(MLP_THREADS, 1)
mlp_kernel(const float* __restrict__ h_in,
           const uint32_t* __restrict__ wfrag,
           const float* __restrict__ b1, const float* __restrict__ b2,
           float* __restrict__ x_out, float* __restrict__ h_out, int n) {
    extern __shared__ __align__(16) uint32_t sm[];
    uint32_t* Hs_hi = sm;
    uint32_t* Hs_lo = sm + 128 * ROWSTRIDE;
    uint32_t* Ts_hi = sm + 2 * 128 * ROWSTRIDE;
    uint32_t* Ts_lo = sm + 3 * 128 * ROWSTRIDE;
    float* stage = (float*)(sm + STAGE_OFF);          // 128x128 f32
    uint32_t stage_b = smem_u32(stage);

    int tid = threadIdx.x, w = tid >> 5, lane = tid & 31;
    int gid = lane >> 2, tg = lane & 3;

    // this warp's weight fragments (128 u32)
    uint2 wB[4][2][8];
    {
        const uint2* wp = (const uint2*)wfrag + (size_t)w * 4 * 2 * 8 * 32;
        #pragma unroll
        for (int img = 0; img < 4; img++)
            #pragma unroll
            for (int nb = 0; nb < 2; nb++)
                #pragma unroll
                for (int ks = 0; ks < 8; ks++)
                    wB[img][nb][ks] = wp[(((img * 2) + nb) * 8 + ks) * 32 + lane];
    }
    float2 b1v[2], b2v[2];
    #pragma unroll
    for (int nb = 0; nb < 2; nb++) {
        b1v[nb] = *(const float2*)(b1 + 16 * w + 8 * nb + 2 * tg);
        b2v[nb] = *(const float2*)(b2 + 16 * w + 8 * nb + 2 * tg);
    }

    int ntiles = (n + TM - 1) / TM;

    // prefetch first tile
    {
        int t = blockIdx.x;
        if (t < ntiles) {
            int row0 = t * TM;
            #pragma unroll
            for (int it = 0; it < 16; it++) {
                int i = tid + it * MLP_THREADS;
                int grow = row0 + (i >> 5);
                if (grow < n) {
                    uint32_t sa = stage_b + i * 16;
                    const float* gp = h_in + (size_t)grow * H + (i & 31) * 4;
                    asm volatile("cp.async.ca.shared.global [%0], [%1], 16;"
                                 :: "r"(sa), "l"(gp));
                }
            }
        }
        asm volatile("cp.async.commit_group;");
    }

    for (int t = blockIdx.x; t < ntiles; t += gridDim.x) {
        int row0 = t * TM;
        asm volatile("cp.async.wait_group 0;" ::: "memory");
        __syncthreads();

        // ---- convert stage -> bf16 hi/lo smem ----
        #pragma unroll 4
        for (int it = 0; it < 16; it++) {
            int i = tid + it * MLP_THREADS;
            int row = i >> 5;
            int c4 = i & 31;
            float4 v = make_float4(0.f, 0.f, 0.f, 0.f);
            if (row0 + row < n) v = ((const float4*)stage)[i];
            __nv_bfloat16 hx = __float2bfloat16(v.x), hy = __float2bfloat16(v.y);
            __nv_bfloat16 hz = __float2bfloat16(v.z), hw = __float2bfloat16(v.w);
            int base = row * ROWSTRIDE;
            int p0 = pidx(2 * c4), p1 = pidx(2 * c4 + 1);
            Hs_hi[base + p0] = pack_bf16(__bfloat162float(hx), __bfloat162float(hy));
            Hs_hi[base + p1] = pack_bf16(__bfloat162float(hz), __bfloat162float(hw));
            Hs_lo[base + p0] = pack_bf16(v.x - __bfloat162float(hx), v.y - __bfloat162float(hy));
            Hs_lo[base + p1] = pack_bf16(v.z - __bfloat162float(hz), v.w - __bfloat162float(hw));
        }
        __syncthreads();

        // ---- prefetch next tile (stage now free) ----
        {
            int tn = t + gridDim.x;
            if (tn < ntiles) {
                int r0n = tn * TM;
                #pragma unroll
                for (int it = 0; it < 16; it++) {
                    int i = tid + it * MLP_THREADS;
                    int grow = r0n + (i >> 5);
                    if (grow < n) {
                        uint32_t sa = stage_b + i * 16;
                        const float* gp = h_in + (size_t)grow * H + (i & 31) * 4;
                        asm volatile("cp.async.ca.shared.global [%0], [%1], 16;"
                                     :: "r"(sa), "l"(gp));
                    }
                }
            }
            asm volatile("cp.async.commit_group;");
        }

        // ---- GEMM1: T = silu(H @ W1 + b1) -> Ts ----
        #pragma unroll 1
        for (int mb = 0; mb < 8; mb++) {
            float acc[2][4] = {{0.f, 0.f, 0.f, 0.f}, {0.f, 0.f, 0.f, 0.f}};
            int ra = (mb * 16 + gid) * ROWSTRIDE;
            int rb = ra + 8 * ROWSTRIDE;
            #pragma unroll
            for (int ks = 0; ks < 8; ks++) {
                uint2 ah  = *(const uint2*)(Hs_hi + ra + ks * 8 + tg * 2);
                uint2 ahb = *(const uint2*)(Hs_hi + rb + ks * 8 + tg * 2);
                uint2 al  = *(const uint2*)(Hs_lo + ra + ks * 8 + tg * 2);
                uint2 alb = *(const uint2*)(Hs_lo + rb + ks * 8 + tg * 2);
                #pragma unroll
                for (int nb = 0; nb < 2; nb++) {
                    uint2 bh = wB[0][nb][ks];
                    uint2 bl = wB[1][nb][ks];
                    MMA_BF16(acc[nb], ah.x, ahb.x, ah.y, ahb.y, bh.x, bh.y);
                    MMA_BF16(acc[nb], al.x, alb.x, al.y, alb.y, bh.x, bh.y);
                    MMA_BF16(acc[nb], ah.x, ahb.x, ah.y, ahb.y, bl.x, bl.y);
                }
            }
            int sa = (mb * 16 + gid) * ROWSTRIDE + 8 * w + 2 * tg;
            int sb = sa + 8 * ROWSTRIDE;
            #pragma unroll
            for (int nb = 0; nb < 2; nb++) {
                float f0 = silu_fast(acc[nb][0] + b1v[nb].x);
                float f1 = silu_fast(acc[nb][1] + b1v[nb].y);
                float f2 = silu_fast(acc[nb][2] + b1v[nb].x);
                float f3 = silu_fast(acc[nb][3] + b1v[nb].y);
                __nv_bfloat16 h0 = __float2bfloat16(f0), h1 = __float2bfloat16(f1);
                __nv_bfloat16 h2 = __float2bfloat16(f2), h3 = __float2bfloat16(f3);
                Ts_hi[sa + nb] = pack_bf16(__bfloat162float(h0), __bfloat162float(h1));
                Ts_hi[sb + nb] = pack_bf16(__bfloat162float(h2), __bfloat162float(h3));
                Ts_lo[sa + nb] = pack_bf16(f0 - __bfloat162float(h0), f1 - __bfloat162float(h1));
                Ts_lo[sb + nb] = pack_bf16(f2 - __bfloat162float(h2), f3 - __bfloat162float(h3));
            }
        }
        __syncthreads();

        // ---- GEMM2: out = T @ W2 + b2 -> gmem ----
        #pragma unroll 1
        for (int mb = 0; mb < 8; mb++) {
            float acc[2][4] = {{0.f, 0.f, 0.f, 0.f}, {0.f, 0.f, 0.f, 0.f}};
            int ra = (mb * 16 + gid) * ROWSTRIDE;
            int rb = ra + 8 * ROWSTRIDE;
            #pragma unroll
            for (int ks = 0; ks < 8; ks++) {
                uint2 ah  = *(const uint2*)(Ts_hi + ra + ks * 8 + tg * 2);
                uint2 ahb = *(const uint2*)(Ts_hi + rb + ks * 8 + tg * 2);
                uint2 al  = *(const uint2*)(Ts_lo + ra + ks * 8 + tg * 2);
                uint2 alb = *(const uint2*)(Ts_lo + rb + ks * 8 + tg * 2);
                #pragma unroll
                for (int nb = 0; nb < 2; nb++) {
                    uint2 bh = wB[2][nb][ks];
                    uint2 bl = wB[3][nb][ks];
                    MMA_BF16(acc[nb], ah.x, ahb.x, ah.y, ahb.y, bh.x, bh.y);
                    MMA_BF16(acc[nb], al.x, alb.x, al.y, alb.y, bh.x, bh.y);
                    MMA_BF16(acc[nb], ah.x, ahb.x, ah.y, ahb.y, bl.x, bl.y);
                }
            }
            int r0 = row0 + mb * 16 + gid;
            int r1 = r0 + 8;
            #pragma unroll
            for (int nb = 0; nb < 2; nb++) {
                int col = 16 * w + 8 * nb + 2 * tg;
                if (r0 < n) {
                    float2 o0 = make_float2(acc[nb][0] + b2v[nb].x,
                                            acc[nb][1] + b2v[nb].y);
                    *(float2*)(x_out + (size_t)r0 * H + col) = o0;
                    if (h_out) *(float2*)(h_out + (size_t)r0 * H + col) = o0;
                }
                if (r1 < n) {
                    float2 o1 = make_float2(acc[nb][2] + b2v[nb].x,
                                            acc[nb][3] + b2v[nb].y);
                    *(float2*)(x_out + (size_t)r1 * H + col) = o1;
                    if (h_out) *(float2*)(h_out + (size_t)r1 * H + col) = o1;
                }
            }
        }
        __syncthreads();
    }
}

// batch_vec -> float tail of the output
__global__ void batch_kernel(const int* __restrict__ bv, float* __restrict__ out, int n) {
    int i = blockIdx.x * blockDim.x + threadIdx.x;
    if (i < n) out[i] = (float)bv[i];
}

extern "C" void kernel_launch(void* const* d_in, const int* in_sizes, int n_in,
                              void* d_out, int out_size) {
    const float* emb       = (const float*)d_in[0];
    const float* We        = (const float*)d_in[1];
    const float* be        = (const float*)d_in[2];
    const float* W1        = (const float*)d_in[3];
    const float* b1        = (const float*)d_in[4];
    const float* W2        = (const float*)d_in[5];
    const float* b2        = (const float*)d_in[6];
    const float* edge_attr = (const float*)d_in[7];
    const int*   z         = (const int*)d_in[8];
    const int*   ei        = (const int*)d_in[9];
    const int*   bv        = (const int*)d_in[10];

    int n = in_sizes[8];
    int E = in_sizes[9] / 2;
    float* out = (float*)d_out;

    float *gx, *gh;
    uint32_t* gwf;
    cudaGetSymbolAddress((void**)&gx, g_x);
    cudaGetSymbolAddress((void**)&gh, g_h);
    cudaGetSymbolAddress((void**)&gwf, g_wfrag);

    cudaFuncSetAttribute(mlp_kernel, cudaFuncAttributeMaxDynamicSharedMemorySize,
                         MLP_SMEM);

    wprep_kernel<<<(3 * 8 * 4 * 2 * 8 * 32 * 2 + 255) / 256, 256>>>(W1, W2);
    embed_kernel<<<(n * 32 + 255) / 256, 256>>>(emb, z, gx, gh, n);

    for (int l = 0; l < 3; l++) {
        edge_kernel<<<4096, 256>>>(gx, gh, edge_attr, ei,
                                   We + (size_t)l * 4 * H, be + (size_t)l * H, E);
        bool last = (l == 2);
        mlp_kernel<<<148, MLP_THREADS, MLP_SMEM>>>(
            gh,
            gwf + (size_t)l * 8 * 4 * 2 * 8 * 32 * 2,
            b1 + (size_t)l * H, b2 + (size_t)l * H,
            last ? out : gx,
            last ? nullptr : gh,
            n);
    }

    if (out_size >= n * H + n) {
        batch_kernel<<<(n + 255) / 256, 256>>>(bv, out + (size_t)n * H, n);
    }
}

// round 5
// speedup vs baseline: 1.8878x; 1.0696x over previous
#include <cuda_runtime.h>
#include <cuda_bf16.h>
#include <cstdint>

#define H 128
#define NMAX 100000
#define TM 128
#define MLP_THREADS 256
#define ROWSTRIDE 72                        // u32 per row: 8-bank row skew -> conflict-free LDS.64
#define STAGE_OFF (4 * 128 * ROWSTRIDE)     // u32 offset of f32 stage buffer
#define MLP_SMEM (STAGE_OFF * 4 + 128 * 128 * 4)  // 147456 + 65536 = 212992 B

// Scratch (device globals: no allocation allowed)
__device__ __align__(16) float g_x[(size_t)NMAX * H];
__device__ __align__(16) float g_h[(size_t)NMAX * H];
// weight fragments: [layer][warp 8][img 4][nb 2][ks 8][lane 32][2] u32
__device__ __align__(16) uint32_t g_wfrag[3 * 8 * 4 * 2 * 8 * 32 * 2];

__device__ __forceinline__ uint32_t pack_bf16(float x, float y) {
    __nv_bfloat162 t = __floats2bfloat162_rn(x, y);
    return *(uint32_t*)&t;
}
// permuted pair index: pair j (cols 2j,2j+1) -> slot so that a0/a2 are adjacent
__device__ __forceinline__ int pidx(int j) {
    return ((j >> 3) << 3) + ((j & 3) << 1) + ((j >> 2) & 1);
}
__device__ __forceinline__ uint32_t smem_u32(const void* p) {
    uint32_t a;
    asm("{ .reg .u64 t; cvta.to.shared.u64 t, %1; cvt.u32.u64 %0, t; }" : "=r"(a) : "l"(p));
    return a;
}
__device__ __forceinline__ float silu_fast(float f) {
    float th;
    asm("tanh.approx.f32 %0, %1;" : "=f"(th) : "f"(0.5f * f));
    return f * fmaf(0.5f, th, 0.5f);
}

#define MMA_BF16(c, A0, A1, A2, A3, B0, B1)                                   \
    asm volatile("mma.sync.aligned.m16n8k16.row.col.f32.bf16.bf16.f32 "       \
                 "{%0,%1,%2,%3}, {%4,%5,%6,%7}, {%8,%9}, {%0,%1,%2,%3};"      \
                 : "+f"(c[0]), "+f"(c[1]), "+f"(c[2]), "+f"(c[3])             \
                 : "r"(A0), "r"(A1), "r"(A2), "r"(A3), "r"(B0), "r"(B1));

// ---------------------------------------------------------------------------
// Weight prep: split W1/W2 (f32 [k][n]) into bf16 hi/lo mma B-fragments,
// laid out exactly in the per-warp register-load order.
// ---------------------------------------------------------------------------
__global__ void wprep_kernel(const float* __restrict__ W1,
                             const float* __restrict__ W2) {
    int idx = blockIdx.x * blockDim.x + threadIdx.x;
    if (idx >= 3 * 8 * 4 * 2 * 8 * 32 * 2) return;
    int r    = idx & 1;
    int lane = (idx >> 1) & 31;
    int ks   = (idx >> 6) & 7;
    int nb   = (idx >> 9) & 1;
    int img  = (idx >> 10) & 3;
    int w    = (idx >> 12) & 7;
    int l    = idx >> 15;
    int gid = lane >> 2, tg = lane & 3;
    int mat = img >> 1, hl = img & 1;
    int n  = w * 16 + nb * 8 + gid;
    int k0 = ks * 16 + tg * 2 + r * 8;
    const float* W = (mat ? W2 : W1) + (size_t)l * H * H;
    float v0 = W[k0 * H + n];
    float v1 = W[(k0 + 1) * H + n];
    __nv_bfloat16 h0 = __float2bfloat16(v0);
    __nv_bfloat16 h1 = __float2bfloat16(v1);
    float o0 = hl ? (v0 - __bfloat162float(h0)) : __bfloat162float(h0);
    float o1 = hl ? (v1 - __bfloat162float(h1)) : __bfloat162float(h1);
    g_wfrag[idx] = pack_bf16(o0, o1);
}

// ---------------------------------------------------------------------------
// Embedding gather
// ---------------------------------------------------------------------------
__global__ void embed_kernel(const float* __restrict__ emb,
                             const int* __restrict__ z,
                             float* __restrict__ x, float* __restrict__ h,
                             int n) {
    int i = blockIdx.x * blockDim.x + threadIdx.x;
    if (i >= n * 32) return;
    int node = i >> 5;
    int c = i & 31;
    float4 v = ((const float4*)emb)[(size_t)z[node] * 32 + c];
    ((float4*)x)[i] = v;
    ((float4*)h)[i] = v;
}

// ---------------------------------------------------------------------------
// Edge/message kernel: one warp per 4 edges (pipelined), lane = 4 channels.
//   e = edge_attr @ We + be ; m = relu(x[src] + e) ; h[dst] += m (red.v4)
// ---------------------------------------------------------------------------
__global__ void edge_kernel(const float* __restrict__ x,
                            float* __restrict__ h,
                            const float* __restrict__ edge_attr,
                            const int* __restrict__ ei,
                            const float* __restrict__ We,
                            const float* __restrict__ be,
                            int E) {
    __shared__ float Wes[4 * H];
    __shared__ float bes[H];
    int tid = threadIdx.x;
    for (int i = tid; i < 4 * H; i += blockDim.x) Wes[i] = We[i];
    for (int i = tid; i < H; i += blockDim.x) bes[i] = be[i];
    __syncthreads();

    int lane = tid & 31;
    int warp = blockIdx.x * (blockDim.x >> 5) + (tid >> 5);
    int nwarps = gridDim.x * (blockDim.x >> 5);

    float4 w0 = ((const float4*)Wes)[0 * 32 + lane];
    float4 w1 = ((const float4*)Wes)[1 * 32 + lane];
    float4 w2 = ((const float4*)Wes)[2 * 32 + lane];
    float4 w3 = ((const float4*)Wes)[3 * 32 + lane];
    float4 bb = ((const float4*)bes)[lane];

    int stride = nwarps * 4;
    #pragma unroll 1
    for (int e0 = warp * 4; e0 < E; e0 += stride) {
        int ne = E - e0; if (ne > 4) ne = 4;
        int s[4], d[4];
        float4 ea[4], xv[4];
        #pragma unroll
        for (int j = 0; j < 4; j++)
            if (j < ne) { s[j] = ei[e0 + j]; d[j] = ei[E + e0 + j]; }
        #pragma unroll
        for (int j = 0; j < 4; j++)
            if (j < ne) ea[j] = ((const float4*)edge_attr)[e0 + j];
        #pragma unroll
        for (int j = 0; j < 4; j++)
            if (j < ne) xv[j] = ((const float4*)x)[(size_t)s[j] * 32 + lane];
        #pragma unroll
        for (int j = 0; j < 4; j++) {
            if (j >= ne) break;
            float m0 = xv[j].x + bb.x + ea[j].x * w0.x + ea[j].y * w1.x + ea[j].z * w2.x + ea[j].w * w3.x;
            float m1 = xv[j].y + bb.y + ea[j].x * w0.y + ea[j].y * w1.y + ea[j].z * w2.y + ea[j].w * w3.y;
            float m2 = xv[j].z + bb.z + ea[j].x * w0.z + ea[j].y * w1.z + ea[j].z * w2.z + ea[j].w * w3.z;
            float m3 = xv[j].w + bb.w + ea[j].x * w0.w + ea[j].y * w1.w + ea[j].z * w2.w + ea[j].w * w3.w;
            m0 = fmaxf(m0, 0.f); m1 = fmaxf(m1, 0.f);
            m2 = fmaxf(m2, 0.f); m3 = fmaxf(m3, 0.f);
            float* dptr = h + (size_t)d[j] * H + lane * 4;
            asm volatile("red.global.add.v4.f32 [%0], {%1,%2,%3,%4};"
                         :: "l"(dptr), "f"(m0), "f"(m1), "f"(m2), "f"(m3)
                         : "memory");
        }
    }
}

// ---------------------------------------------------------------------------
// Fused 2-layer MLP via mma.sync bf16x3: D = Ah*Bh + Al*Bh + Ah*Bl
// Persistent CTAs, 128-row tiles, cp.async-prefetched stage buffer,
// tanh-based silu, conflict-free smem layout (ROWSTRIDE=72).
// ---------------------------------------------------------------------------
__global__ void __launch_bounds__(MLP_THREADS, 1)
mlp_kernel(const float* __restrict__ h_in,
           const uint32_t* __restrict__ wfrag,
           const float* __restrict__ b1, const float* __restrict__ b2,
           float* __restrict__ x_out, float* __restrict__ h_out, int n) {
    extern __shared__ __align__(16) uint32_t sm[];
    uint32_t* Hs_hi = sm;
    uint32_t* Hs_lo = sm + 128 * ROWSTRIDE;
    uint32_t* Ts_hi = sm + 2 * 128 * ROWSTRIDE;
    uint32_t* Ts_lo = sm + 3 * 128 * ROWSTRIDE;
    float* stage = (float*)(sm + STAGE_OFF);          // 128x128 f32
    uint32_t stage_b = smem_u32(stage);

    int tid = threadIdx.x, w = tid >> 5, lane = tid & 31;
    int gid = lane >> 2, tg = lane & 3;

    // this warp's weight fragments (128 u32)
    uint2 wB[4][2][8];
    {
        const uint2* wp = (const uint2*)wfrag + (size_t)w * 4 * 2 * 8 * 32;
        #pragma unroll
        for (int img = 0; img < 4; img++)
            #pragma unroll
            for (int nb = 0; nb < 2; nb++)
                #pragma unroll
                for (int ks = 0; ks < 8; ks++)
                    wB[img][nb][ks] = wp[(((img * 2) + nb) * 8 + ks) * 32 + lane];
    }
    float2 b1v[2], b2v[2];
    #pragma unroll
    for (int nb = 0; nb < 2; nb++) {
        b1v[nb] = *(const float2*)(b1 + 16 * w + 8 * nb + 2 * tg);
        b2v[nb] = *(const float2*)(b2 + 16 * w + 8 * nb + 2 * tg);
    }

    int ntiles = (n + TM - 1) / TM;

    // prefetch first tile
    {
        int t = blockIdx.x;
        if (t < ntiles) {
            int row0 = t * TM;
            #pragma unroll
            for (int it = 0; it < 16; it++) {
                int i = tid + it * MLP_THREADS;
                int grow = row0 + (i >> 5);
                if (grow < n) {
                    uint32_t sa = stage_b + i * 16;
                    const float* gp = h_in + (size_t)grow * H + (i & 31) * 4;
                    asm volatile("cp.async.ca.shared.global [%0], [%1], 16;"
                                 :: "r"(sa), "l"(gp));
                }
            }
        }
        asm volatile("cp.async.commit_group;");
    }

    for (int t = blockIdx.x; t < ntiles; t += gridDim.x) {
        int row0 = t * TM;
        asm volatile("cp.async.wait_group 0;" ::: "memory");
        __syncthreads();

        // ---- convert stage -> bf16 hi/lo smem ----
        #pragma unroll 4
        for (int it = 0; it < 16; it++) {
            int i = tid + it * MLP_THREADS;
            int row = i >> 5;
            int c4 = i & 31;
            float4 v = make_float4(0.f, 0.f, 0.f, 0.f);
            if (row0 + row < n) v = ((const float4*)stage)[i];
            __nv_bfloat16 hx = __float2bfloat16(v.x), hy = __float2bfloat16(v.y);
            __nv_bfloat16 hz = __float2bfloat16(v.z), hw = __float2bfloat16(v.w);
            int base = row * ROWSTRIDE;
            int p0 = pidx(2 * c4), p1 = pidx(2 * c4 + 1);
            Hs_hi[base + p0] = pack_bf16(__bfloat162float(hx), __bfloat162float(hy));
            Hs_hi[base + p1] = pack_bf16(__bfloat162float(hz), __bfloat162float(hw));
            Hs_lo[base + p0] = pack_bf16(v.x - __bfloat162float(hx), v.y - __bfloat162float(hy));
            Hs_lo[base + p1] = pack_bf16(v.z - __bfloat162float(hz), v.w - __bfloat162float(hw));
        }
        __syncthreads();

        // ---- prefetch next tile (stage now free) ----
        {
            int tn = t + gridDim.x;
            if (tn < ntiles) {
                int r0n = tn * TM;
                #pragma unroll
                for (int it = 0; it < 16; it++) {
                    int i = tid + it * MLP_THREADS;
                    int grow = r0n + (i >> 5);
                    if (grow < n) {
                        uint32_t sa = stage_b + i * 16;
                        const float* gp = h_in + (size_t)grow * H + (i & 31) * 4;
                        asm volatile("cp.async.ca.shared.global [%0], [%1], 16;"
                                     :: "r"(sa), "l"(gp));
                    }
                }
            }
            asm volatile("cp.async.commit_group;");
        }

        // ---- GEMM1: T = silu(H @ W1 + b1) -> Ts ----
        #pragma unroll 1
        for (int mb = 0; mb < 8; mb++) {
            float acc[2][4] = {{0.f, 0.f, 0.f, 0.f}, {0.f, 0.f, 0.f, 0.f}};
            int ra = (mb * 16 + gid) * ROWSTRIDE;
            int rb = ra + 8 * ROWSTRIDE;
            #pragma unroll
            for (int ks = 0; ks < 8; ks++) {
                uint2 ah  = *(const uint2*)(Hs_hi + ra + ks * 8 + tg * 2);
                uint2 ahb = *(const uint2*)(Hs_hi + rb + ks * 8 + tg * 2);
                uint2 al  = *(const uint2*)(Hs_lo + ra + ks * 8 + tg * 2);
                uint2 alb = *(const uint2*)(Hs_lo + rb + ks * 8 + tg * 2);
                #pragma unroll
                for (int nb = 0; nb < 2; nb++) {
                    uint2 bh = wB[0][nb][ks];
                    uint2 bl = wB[1][nb][ks];
                    MMA_BF16(acc[nb], ah.x, ahb.x, ah.y, ahb.y, bh.x, bh.y);
                    MMA_BF16(acc[nb], al.x, alb.x, al.y, alb.y, bh.x, bh.y);
                    MMA_BF16(acc[nb], ah.x, ahb.x, ah.y, ahb.y, bl.x, bl.y);
                }
            }
            int sa = (mb * 16 + gid) * ROWSTRIDE + 8 * w + 2 * tg;
            int sb = sa + 8 * ROWSTRIDE;
            #pragma unroll
            for (int nb = 0; nb < 2; nb++) {
                float f0 = silu_fast(acc[nb][0] + b1v[nb].x);
                float f1 = silu_fast(acc[nb][1] + b1v[nb].y);
                float f2 = silu_fast(acc[nb][2] + b1v[nb].x);
                float f3 = silu_fast(acc[nb][3] + b1v[nb].y);
                __nv_bfloat16 h0 = __float2bfloat16(f0), h1 = __float2bfloat16(f1);
                __nv_bfloat16 h2 = __float2bfloat16(f2), h3 = __float2bfloat16(f3);
                Ts_hi[sa + nb] = pack_bf16(__bfloat162float(h0), __bfloat162float(h1));
                Ts_hi[sb + nb] = pack_bf16(__bfloat162float(h2), __bfloat162float(h3));
                Ts_lo[sa + nb] = pack_bf16(f0 - __bfloat162float(h0), f1 - __bfloat162float(h1));
                Ts_lo[sb + nb] = pack_bf16(f2 - __bfloat162float(h2), f3 - __bfloat162float(h3));
            }
        }
        __syncthreads();

        // ---- GEMM2: out = T @ W2 + b2 -> gmem ----
        #pragma unroll 1
        for (int mb = 0; mb < 8; mb++) {
            float acc[2][4] = {{0.f, 0.f, 0.f, 0.f}, {0.f, 0.f, 0.f, 0.f}};
            int ra = (mb * 16 + gid) * ROWSTRIDE;
            int rb = ra + 8 * ROWSTRIDE;
            #pragma unroll
            for (int ks = 0; ks < 8; ks++) {
                uint2 ah  = *(const uint2*)(Ts_hi + ra + ks * 8 + tg * 2);
                uint2 ahb = *(const uint2*)(Ts_hi + rb + ks * 8 + tg * 2);
                uint2 al  = *(const uint2*)(Ts_lo + ra + ks * 8 + tg * 2);
                uint2 alb = *(const uint2*)(Ts_lo + rb + ks * 8 + tg * 2);
                #pragma unroll
                for (int nb = 0; nb < 2; nb++) {
                    uint2 bh = wB[2][nb][ks];
                    uint2 bl = wB[3][nb][ks];
                    MMA_BF16(acc[nb], ah.x, ahb.x, ah.y, ahb.y, bh.x, bh.y);
                    MMA_BF16(acc[nb], al.x, alb.x, al.y, alb.y, bh.x, bh.y);
                    MMA_BF16(acc[nb], ah.x, ahb.x, ah.y, ahb.y, bl.x, bl.y);
                }
            }
            int r0 = row0 + mb * 16 + gid;
            int r1 = r0 + 8;
            #pragma unroll
            for (int nb = 0; nb < 2; nb++) {
                int col = 16 * w + 8 * nb + 2 * tg;
                if (r0 < n) {
                    float2 o0 = make_float2(acc[nb][0] + b2v[nb].x,
                                            acc[nb][1] + b2v[nb].y);
                    *(float2*)(x_out + (size_t)r0 * H + col) = o0;
                    if (h_out) *(float2*)(h_out + (size_t)r0 * H + col) = o0;
                }
                if (r1 < n) {
                    float2 o1 = make_float2(acc[nb][2] + b2v[nb].x,
                                            acc[nb][3] + b2v[nb].y);
                    *(float2*)(x_out + (size_t)r1 * H + col) = o1;
                    if (h_out) *(float2*)(h_out + (size_t)r1 * H + col) = o1;
                }
            }
        }
        __syncthreads();
    }
}

// batch_vec -> float tail of the output
__global__ void batch_kernel(const int* __restrict__ bv, float* __restrict__ out, int n) {
    int i = blockIdx.x * blockDim.x + threadIdx.x;
    if (i < n) out[i] = (float)bv[i];
}

extern "C" void kernel_launch(void* const* d_in, const int* in_sizes, int n_in,
                              void* d_out, int out_size) {
    const float* emb       = (const float*)d_in[0];
    const float* We        = (const float*)d_in[1];
    const float* be        = (const float*)d_in[2];
    const float* W1        = (const float*)d_in[3];
    const float* b1        = (const float*)d_in[4];
    const float* W2        = (const float*)d_in[5];
    const float* b2        = (const float*)d_in[6];
    const float* edge_attr = (const float*)d_in[7];
    const int*   z         = (const int*)d_in[8];
    const int*   ei        = (const int*)d_in[9];
    const int*   bv        = (const int*)d_in[10];

    int n = in_sizes[8];
    int E = in_sizes[9] / 2;
    float* out = (float*)d_out;

    float *gx, *gh;
    uint32_t* gwf;
    cudaGetSymbolAddress((void**)&gx, g_x);
    cudaGetSymbolAddress((void**)&gh, g_h);
    cudaGetSymbolAddress((void**)&gwf, g_wfrag);

    cudaFuncSetAttribute(mlp_kernel, cudaFuncAttributeMaxDynamicSharedMemorySize,
                         MLP_SMEM);

    wprep_kernel<<<(3 * 8 * 4 * 2 * 8 * 32 * 2 + 255) / 256, 256>>>(W1, W2);
    embed_kernel<<<(n * 32 + 255) / 256, 256>>>(emb, z, gx, gh, n);

    for (int l = 0; l < 3; l++) {
        edge_kernel<<<4096, 256>>>(gx, gh, edge_attr, ei,
                                   We + (size_t)l * 4 * H, be + (size_t)l * H, E);
        bool last = (l == 2);
        mlp_kernel<<<148, MLP_THREADS, MLP_SMEM>>>(
            gh,
            gwf + (size_t)l * 8 * 4 * 2 * 8 * 32 * 2,
            b1 + (size_t)l * H, b2 + (size_t)l * H,
            last ? out : gx,
            last ? nullptr : gh,
            n);
    }

    if (out_size >= n * H + n) {
        batch_kernel<<<(n + 255) / 256, 256>>>(bv, out + (size_t)n * H, n);
    }
}